// round 16
// baseline (speedup 1.0000x reference)
#include <cuda_runtime.h>
#include <math.h>

#define N_LIG 1024
#define N_POK 8192
#define D     256
#define ADIM  512
#define NH    4
#define HD    64

#define NTAB      8192
#define TAB_SCALE (NTAB / 10.0f)     // d in [0,10) -> index
#define TAB_INV   (10.0f / NTAB)
#define TAB_BLOCKS ((NTAB + 1 + 255) / 256)   // 33

#define KSTRIDE 257                  // padded smem row stride (conflict-free LDS)

// ---------------- device scratch (no allocations allowed) ----------------
__device__ float  g_K[N_POK * D];
__device__ float  g_V[N_POK * D];
__device__ int    g_nbr[(size_t)N_LIG * N_POK];
__device__ float4 g_geo[(size_t)N_LIG * N_POK];   // (ux, uy, uz, d) per compacted pair
__device__ int    g_cnt[N_LIG];
__device__ float4 g_tab[NTAB + 1];                // edge_attr(d) + e2b, per head

// ---------------- tiled FP32 GEMM: C[M,N] = A[M,K] @ W[K,N] + bias ----------------
#define BM 128
#define BN 64
#define BK 16

__global__ __launch_bounds__(256) void gemm_bias_kernel(
    const float* __restrict__ A, const float* __restrict__ W,
    const float* __restrict__ bias, float* __restrict__ C,
    int M, int N, int K)
{
    __shared__ float As[BK][BM + 4];
    __shared__ float Bs[BK][BN];

    const int tid = threadIdx.x;
    const int bm = blockIdx.y * BM;
    const int bn = blockIdx.x * BN;
    const int tx = tid & 15;        // 0..15 -> 4 output cols each
    const int ty = tid >> 4;        // 0..15 -> 8 output rows each

    float acc[8][4];
#pragma unroll
    for (int m = 0; m < 8; m++)
#pragma unroll
        for (int n = 0; n < 4; n++) acc[m][n] = 0.f;

    for (int k0 = 0; k0 < K; k0 += BK) {
#pragma unroll
        for (int ld = 0; ld < 2; ld++) {
            int f = tid * 2 + ld;
            int row = f >> 2;
            int c4 = (f & 3) * 4;
            float4 v = *(const float4*)(A + (size_t)(bm + row) * K + k0 + c4);
            As[c4 + 0][row] = v.x;
            As[c4 + 1][row] = v.y;
            As[c4 + 2][row] = v.z;
            As[c4 + 3][row] = v.w;
        }
        {
            int r = tid >> 4;
            int c4 = (tid & 15) * 4;
            *(float4*)(&Bs[r][c4]) = *(const float4*)(W + (size_t)(k0 + r) * N + bn + c4);
        }
        __syncthreads();

#pragma unroll
        for (int kk = 0; kk < BK; kk++) {
            float a[8], b[4];
            *(float4*)(a)     = *(const float4*)(&As[kk][ty * 8]);
            *(float4*)(a + 4) = *(const float4*)(&As[kk][ty * 8 + 4]);
            *(float4*)(b)     = *(const float4*)(&Bs[kk][tx * 4]);
#pragma unroll
            for (int m = 0; m < 8; m++)
#pragma unroll
                for (int n = 0; n < 4; n++)
                    acc[m][n] = fmaf(a[m], b[n], acc[m][n]);
        }
        __syncthreads();
    }

    float4 bv = *(const float4*)(bias + bn + tx * 4);
#pragma unroll
    for (int m = 0; m < 8; m++) {
        int row = bm + ty * 8 + m;
        float4 ov;
        ov.x = acc[m][0] + bv.x;
        ov.y = acc[m][1] + bv.y;
        ov.z = acc[m][2] + bv.z;
        ov.w = acc[m][3] + bv.w;
        *(float4*)(C + (size_t)row * N + bn + tx * 4) = ov;
    }
}

// ---------------- fused: neighbor compaction (blocks < N_LIG) + edge table (rest) ----------------
__global__ __launch_bounds__(256) void compact_tab_kernel(
    const float* __restrict__ x_lig, const float* __restrict__ x_pok,
    const float* __restrict__ e1w, const float* __restrict__ e1b,
    const float* __restrict__ e2w, const float* __restrict__ e2b)
{
    const int tid  = threadIdx.x;

    if (blockIdx.x >= N_LIG) {
        const int entry = (blockIdx.x - N_LIG) * 256 + tid;
        if (entry <= NTAB) {
            const float d = entry * TAB_INV;
            float a0 = 0.f, a1 = 0.f, a2 = 0.f, a3 = 0.f;
            for (int k = 0; k < D; k++) {
                float t  = fmaf(d, e1w[k], e1b[k]);
                float sv = __fdividef(t, 1.f + __expf(-t));
                float4 w4 = *(const float4*)(&e2w[k * 4]);
                a0 = fmaf(sv, w4.x, a0);
                a1 = fmaf(sv, w4.y, a1);
                a2 = fmaf(sv, w4.z, a2);
                a3 = fmaf(sv, w4.w, a3);
            }
            g_tab[entry] = make_float4(a0 + e2b[0], a1 + e2b[1], a2 + e2b[2], a3 + e2b[3]);
        }
        return;
    }

    const int i    = blockIdx.x;
    const int lane = tid & 31;
    const int w    = tid >> 5;          // 8 warps
    const int SPAN = N_POK / 8;         // 1024 pockets per warp

    __shared__ int sCnt[8], sOff[8];

    const float xi0 = x_lig[i * 3 + 0];
    const float xi1 = x_lig[i * 3 + 1];
    const float xi2 = x_lig[i * 3 + 2];
    const int j0 = w * SPAN;

    int cnt = 0;
    for (int c = 0; c < SPAN; c += 32) {
        int j = j0 + c + lane;
        float r0 = x_pok[j * 3 + 0] - xi0;
        float r1 = x_pok[j * 3 + 1] - xi1;
        float r2 = x_pok[j * 3 + 2] - xi2;
        float d = sqrtf(r0 * r0 + r1 * r1 + r2 * r2);
        cnt += __popc(__ballot_sync(0xffffffffu, d < 10.0f));
    }
    if (lane == 0) sCnt[w] = cnt;
    __syncthreads();
    if (tid == 0) {
        int a = 0;
#pragma unroll
        for (int k = 0; k < 8; k++) { sOff[k] = a; a += sCnt[k]; }
        g_cnt[i] = a;
    }
    __syncthreads();

    int base = sOff[w];
    int*    row = g_nbr + (size_t)i * N_POK;
    float4* geo = g_geo + (size_t)i * N_POK;
    for (int c = 0; c < SPAN; c += 32) {
        int j = j0 + c + lane;
        float r0 = x_pok[j * 3 + 0] - xi0;
        float r1 = x_pok[j * 3 + 1] - xi1;
        float r2 = x_pok[j * 3 + 2] - xi2;
        float d = sqrtf(r0 * r0 + r1 * r1 + r2 * r2);
        bool m = d < 10.0f;
        unsigned bal = __ballot_sync(0xffffffffu, m);
        if (m) {
            int p = base + __popc(bal & ((1u << lane) - 1u));
            row[p] = j;
            float inv = __fdividef(1.f, d + 1e-8f);
            geo[p] = make_float4(r0 * inv, r1 * inv, r2 * inv, d);
        }
        base += __popc(bal);
    }
}

// ---------------- fused attention + Q projection + epilogue: 1 block per ligand ----------------
__global__ __launch_bounds__(256) void attn_kernel(
    const float* __restrict__ h_lig, const float* __restrict__ x_lig,
    const float* __restrict__ qw,  const float* __restrict__ qb,
    const float* __restrict__ ow,  const float* __restrict__ ob,
    const float* __restrict__ c1w, const float* __restrict__ c1b,
    const float* __restrict__ c2w, const float* __restrict__ c2b,
    float* __restrict__ out)
{
    const int i    = blockIdx.x;
    const int tid  = threadIdx.x;      // 256
    const int lane = tid & 31;
    const int wrp  = tid >> 5;         // 8 warps
    const int hh   = tid >> 6;         // head of this output element

    __shared__ float sK[32 * KSTRIDE];   // staged K tile (padded rows)
    __shared__ float sQ[D];
    __shared__ float sS[32 * 4];       // tile scores [j][h]
    __shared__ float sP[32 * 4];       // tile probs  [j][h]
    __shared__ float sU[32 * 3];       // unit rel-pos
    __shared__ float sD[32];           // distances
    __shared__ int   sJ[32];
    __shared__ float sM[4], sL[4], sAl[4];
    __shared__ float sC[12];           // coord numerators [h][dim]
    __shared__ float sHa[D];           // (prologue: h_lig row; finale: h_attended)
    __shared__ float sRed[8];

    // ---- prologue: Q projection for this ligand (Q = h @ qw + qb) ----
    sHa[tid] = h_lig[(size_t)i * D + tid];
    if (tid < 4)  { sM[tid] = -INFINITY; sL[tid] = 0.f; }
    if (tid < 12) sC[tid] = 0.f;
    __syncthreads();

    {
        float qacc = qb[tid];
#pragma unroll 8
        for (int k = 0; k < D; k++)
            qacc = fmaf(sHa[k], qw[(size_t)k * D + tid], qacc);
        sQ[tid] = qacc;
    }

    float o = 0.f;   // this thread's output element (dim tid)
    const int cnt = g_cnt[i];
    __syncthreads();

    const int jrow = tid >> 3;     // staging: row 0..31
    const int c8   = tid & 7;      // staging: 8 threads per row

    for (int t0 = 0; t0 < cnt; t0 += 32) {
        const int tn = min(32, cnt - t0);
        if (tid < tn) {
            sJ[tid] = g_nbr[(size_t)i * N_POK + t0 + tid];
            float4 g = g_geo[(size_t)i * N_POK + t0 + tid];
            sU[tid * 3 + 0] = g.x;
            sU[tid * 3 + 1] = g.y;
            sU[tid * 3 + 2] = g.z;
            sD[tid] = g.w;
        }
        __syncthreads();

        // ---- phase A1: stage K tile into smem (coalesced, 8 threads/row) ----
        if (jrow < tn) {
            const float* Kr = g_K + (size_t)sJ[jrow] * D;
            float* dst = &sK[jrow * KSTRIDE];
#pragma unroll
            for (int ii = 0; ii < 16; ii++) {
                int f2 = ii * 8 + c8;                  // float2 index 0..127
                float2 v = *(const float2*)(Kr + f2 * 2);
                dst[f2 * 2]     = v.x;
                dst[f2 * 2 + 1] = v.y;
            }
        }
        __syncthreads();

        // ---- phase A2: reduction-free scores; thread (j=lane, h=wrp<4) ----
        if (wrp < 4 && lane < tn) {
            const float* krow = &sK[lane * KSTRIDE + wrp * 64];
            const float* qrow = &sQ[wrp * 64];        // broadcast
            float s = 0.f;
#pragma unroll 16
            for (int k = 0; k < 64; k++)
                s = fmaf(qrow[k], krow[k], s);
            float t = sD[lane] * TAB_SCALE;
            int it = min((int)t, NTAB - 1);
            float fr = t - (float)it;
            float4 ea = g_tab[it];
            float4 eb = g_tab[it + 1];
            float bias = (wrp == 0) ? fmaf(fr, eb.x - ea.x, ea.x)
                       : (wrp == 1) ? fmaf(fr, eb.y - ea.y, ea.y)
                       : (wrp == 2) ? fmaf(fr, eb.z - ea.z, ea.z)
                                    : fmaf(fr, eb.w - ea.w, ea.w);
            sS[lane * 4 + wrp] = fmaf(s, 0.125f, bias);
        }
        __syncthreads();

        // ---- phase B: online softmax bookkeeping, one warp per head ----
        if (wrp < 4) {
            const int h2 = wrp;
            float v = (lane < tn) ? sS[lane * 4 + h2] : -INFINITY;
            float mx = v;
#pragma unroll
            for (int off = 16; off; off >>= 1)
                mx = fmaxf(mx, __shfl_xor_sync(0xffffffffu, mx, off));
            float mold = sM[h2];
            float mnew = fmaxf(mold, mx);
            float p = (lane < tn) ? __expf(v - mnew) : 0.f;
            sP[lane * 4 + h2] = p;
            float sum = p;
#pragma unroll
            for (int off = 16; off; off >>= 1)
                sum += __shfl_xor_sync(0xffffffffu, sum, off);
            if (lane == 0) {
                float al = __expf(mold - mnew);   // 0 on first tile
                sAl[h2] = al;
                sL[h2]  = sL[h2] * al + sum;
                sM[h2]  = mnew;
            }
        }
        __syncthreads();

        // ---- phase C: accumulate V (all 256 threads) + coord numerators ----
        {
            float al = sAl[hh];
            o *= al;
            int jj = 0;
            for (; jj + 4 <= tn; jj += 4) {
                int j0 = sJ[jj], j1 = sJ[jj + 1], j2 = sJ[jj + 2], j3 = sJ[jj + 3];
                float p0 = sP[(jj + 0) * 4 + hh];
                float p1 = sP[(jj + 1) * 4 + hh];
                float p2 = sP[(jj + 2) * 4 + hh];
                float p3 = sP[(jj + 3) * 4 + hh];
                float v0 = g_V[(size_t)j0 * D + tid];
                float v1 = g_V[(size_t)j1 * D + tid];
                float v2 = g_V[(size_t)j2 * D + tid];
                float v3 = g_V[(size_t)j3 * D + tid];
                o = fmaf(p0, v0, o);
                o = fmaf(p1, v1, o);
                o = fmaf(p2, v2, o);
                o = fmaf(p3, v3, o);
            }
            for (; jj < tn; jj++)
                o = fmaf(sP[jj * 4 + hh], g_V[(size_t)sJ[jj] * D + tid], o);
        }
        if (tid < 12) {
            int h2 = tid / 3, dd = tid - h2 * 3;
            float c = sC[tid] * sAl[h2];
            for (int jj = 0; jj < tn; jj++)
                c = fmaf(sP[jj * 4 + h2], sU[jj * 3 + dd], c);
            sC[tid] = c;
        }
        __syncthreads();
    }

    // ---- finalize: normalize, epilogue matvecs, coord update ----
    float l  = sL[hh];
    float ha = (l > 0.f) ? o * __fdividef(1.f, l) : 0.f;   // nan_to_num for empty rows
    __syncthreads();          // all reads of sHa (h_lig) done; safe to overwrite
    sHa[tid] = ha;
    __syncthreads();

    // h_out = h_lig + h_attended @ ow + ob
    float acc = ob[tid];
#pragma unroll 8
    for (int k = 0; k < D; k++)
        acc = fmaf(sHa[k], ow[(size_t)k * D + tid], acc);
    out[(size_t)i * D + tid] = h_lig[(size_t)i * D + tid] + acc;

    // coord_scale = silu(h_attended @ c1w + c1b) @ c2w + c2b
    float acc2 = c1b[tid];
#pragma unroll 8
    for (int k = 0; k < D; k++)
        acc2 = fmaf(sHa[k], c1w[(size_t)k * D + tid], acc2);
    float z = __fdividef(acc2, 1.f + __expf(-acc2)) * c2w[tid];
#pragma unroll
    for (int off = 16; off; off >>= 1)
        z += __shfl_xor_sync(0xffffffffu, z, off);
    if (lane == 0) sRed[wrp] = z;
    __syncthreads();

    if (tid == 0) {
        float sc = c2b[0];
#pragma unroll
        for (int r = 0; r < 8; r++) sc += sRed[r];
        float* ox = out + (size_t)N_LIG * D;
#pragma unroll
        for (int dd = 0; dd < 3; dd++) {
            float cm = 0.f;
#pragma unroll
            for (int h2 = 0; h2 < 4; h2++) {
                float lh = sL[h2];
                if (lh > 0.f) cm += __fdividef(sC[h2 * 3 + dd], lh);
            }
            cm *= 0.25f;   // mean over heads
            ox[i * 3 + dd] = x_lig[i * 3 + dd] + sc * cm;
        }
    }
}

// ---------------- launch ----------------
extern "C" void kernel_launch(void* const* d_in, const int* in_sizes, int n_in,
                              void* d_out, int out_size)
{
    const float* h_lig = (const float*)d_in[0];
    const float* x_lig = (const float*)d_in[1];
    const float* h_ato = (const float*)d_in[2];
    const float* x_pok = (const float*)d_in[3];
    const float* qw  = (const float*)d_in[4];
    const float* qb  = (const float*)d_in[5];
    const float* kw  = (const float*)d_in[6];
    const float* kb  = (const float*)d_in[7];
    const float* vw  = (const float*)d_in[8];
    const float* vb  = (const float*)d_in[9];
    const float* ow  = (const float*)d_in[10];
    const float* ob  = (const float*)d_in[11];
    const float* e1w = (const float*)d_in[12];
    const float* e1b = (const float*)d_in[13];
    const float* e2w = (const float*)d_in[14];
    const float* e2b = (const float*)d_in[15];
    const float* c1w = (const float*)d_in[16];
    const float* c1b = (const float*)d_in[17];
    const float* c2w = (const float*)d_in[18];
    const float* c2b = (const float*)d_in[19];
    float* out = (float*)d_out;

    void *pK, *pV;
    cudaGetSymbolAddress(&pK, g_K);
    cudaGetSymbolAddress(&pV, g_V);

    // launch 1: fused compaction + edge-attr table
    compact_tab_kernel<<<N_LIG + TAB_BLOCKS, 256>>>(x_lig, x_pok, e1w, e1b, e2w, e2b);

    // launches 2-3: K / V projections
    gemm_bias_kernel<<<dim3(D / BN, N_POK / BM), 256>>>(h_ato, kw, kb, (float*)pK, N_POK, D, ADIM);
    gemm_bias_kernel<<<dim3(D / BN, N_POK / BM), 256>>>(h_ato, vw, vb, (float*)pV, N_POK, D, ADIM);

    // launch 4: fused Q projection + attention + epilogue  (profiler window target)
    attn_kernel<<<N_LIG, 256>>>(h_lig, x_lig, qw, qb,
                                ow, ob, c1w, c1b, c2w, c2b, out);
}